// round 14
// baseline (speedup 1.0000x reference)
#include <cuda_runtime.h>
#include <cstdint>
#include <cstddef>

// Problem constants
#define Bb 64
#define Tt 2048
#define Ii 128
#define Hh 256
#define Oo 128
#define Mm 256   // H - K1 + 1

#define NCHUNK 8
#define TCHUNK (Tt / NCHUNK)        // 256
#define TCDIV  (TCHUNK / 128)       // 2

// ---------------- scratch (device globals; no allocation allowed) ----------------
__device__ float g_uhats[Mm * Hh];
__device__ float g_vhats[Mm * Hh];
__device__ float g_bu[Mm];
__device__ float g_bv[Mm];
__device__ float g_U[Hh * Hh];
__device__ float g_V[Hh * Hh];
__device__ float g_W[Hh * Hh];
__device__ float g_xproj[(size_t)Bb * Tt * Hh];  // [B,T,H]
__device__ float g_hall [(size_t)Bb * Tt * Hh];  // [B,T,H]

// ---------------- packed f32x2 helpers ----------------
__device__ __forceinline__ unsigned long long pack2(float lo, float hi) {
    unsigned long long r;
    asm("mov.b64 %0, {%1, %2};" : "=l"(r) : "f"(lo), "f"(hi));
    return r;
}
__device__ __forceinline__ void fma2(unsigned long long& d,
                                     unsigned long long a,
                                     unsigned long long b) {
    asm("fma.rn.f32x2 %0, %1, %2, %0;" : "+l"(d) : "l"(a), "l"(b));
}
__device__ __forceinline__ float2 unpack2(unsigned long long v) {
    float lo, hi;
    asm("mov.b64 {%0, %1}, %2;" : "=f"(lo), "=f"(hi) : "l"(v));
    return make_float2(lo, hi);
}

// ============================================================================
// Kernel 1: build u_hats / v_hats (mask + flips) and betas = 2/<u,u>
// ============================================================================
__global__ __launch_bounds__(256) void prep_kernel(const float* __restrict__ u_raw,
                                                   const float* __restrict__ v_raw) {
    __shared__ float red[256];
    int i = blockIdx.x & 255;
    bool isv = blockIdx.x >= 256;
    int j = threadIdx.x;
    float val = 0.f;
    if (!isv) {
        if (j >= 255 - i) val = u_raw[i * Hh + (255 - j)];
        g_uhats[i * Hh + j] = val;
    } else {
        if (j >= i) val = v_raw[(255 - i) * Hh + (255 - j)];
        g_vhats[i * Hh + j] = val;
    }
    red[j] = val * val;
    __syncthreads();
    for (int s = 128; s > 0; s >>= 1) {
        if (j < s) red[j] += red[j + s];
        __syncthreads();
    }
    if (j == 0) {
        float beta = 2.f / red[0];
        if (isv) g_bv[i] = beta; else g_bu[i] = beta;
    }
}

// ============================================================================
// Kernel 2: Householder chains, one warp per column of U/V.
// ============================================================================
__global__ __launch_bounds__(256) void chain_kernel() {
    int warp = (blockIdx.x * blockDim.x + threadIdx.x) >> 5;
    int lane = threadIdx.x & 31;
    int col = warp & 255;
    bool isv = warp >= 256;
    const float* hats  = isv ? g_vhats : g_uhats;
    const float* betas = isv ? g_bv    : g_bu;
    float* out         = isv ? g_V     : g_U;

    float c[8];
#pragma unroll
    for (int q = 0; q < 8; q++) c[q] = ((lane + 32 * q) == col) ? 1.f : 0.f;

    for (int i = 0; i < Mm; i++) {
        float u[8];
#pragma unroll
        for (int q = 0; q < 8; q++) u[q] = hats[i * Hh + lane + 32 * q];
        float s = 0.f;
#pragma unroll
        for (int q = 0; q < 8; q++) s = fmaf(u[q], c[q], s);
#pragma unroll
        for (int off = 16; off > 0; off >>= 1)
            s += __shfl_xor_sync(0xffffffffu, s, off);
        float sc = betas[i] * s;
#pragma unroll
        for (int q = 0; q < 8; q++) c[q] = fmaf(-sc, u[q], c[q]);
    }
#pragma unroll
    for (int q = 0; q < 8; q++) out[(size_t)(lane + 32 * q) * Hh + col] = c[q];
}

// ============================================================================
// Kernel 3: W = (U * diag(sigmas)) @ V.
// ============================================================================
__global__ __launch_bounds__(256) void wgemm_kernel(const float* __restrict__ sig) {
    __shared__ float su[Hh];
    int r = blockIdx.x;
    int cidx = threadIdx.x;
    su[cidx] = g_U[r * Hh + cidx] * sig[cidx];
    __syncthreads();
    float acc = 0.f;
#pragma unroll 8
    for (int k = 0; k < Hh; k++) acc = fmaf(su[k], g_V[(size_t)k * Hh + cidx], acc);
    g_W[r * Hh + cidx] = acc;
}

// ============================================================================
// Kernel 4/6: chunked SGEMM.  C[m, n] = A[m, :K] . B[n, :K] + bias[n]
// ============================================================================
__global__ __launch_bounds__(256) void sgemm_chunk(const float* __restrict__ A,
                                                   const float* __restrict__ Bm,
                                                   const float* __restrict__ bias,
                                                   float* __restrict__ C,
                                                   int N, int K, int t0) {
    __shared__ float As[16][128];
    __shared__ float Bs[16][128];
    int tid = threadIdx.x;
    int bb = blockIdx.y / TCDIV;
    int tb = blockIdx.y % TCDIV;
    size_t m0 = (size_t)bb * Tt + t0 + tb * 128;
    int n0 = blockIdx.x * 128;
    int tx = tid & 15;
    int ty = tid >> 4;

    float acc[8][8];
#pragma unroll
    for (int i = 0; i < 8; i++)
#pragma unroll
        for (int j = 0; j < 8; j++) acc[i][j] = 0.f;

    for (int k0 = 0; k0 < K; k0 += 16) {
#pragma unroll
        for (int i = 0; i < 2; i++) {
            int fid = tid + i * 256;
            int row = fid >> 2;
            int c4  = fid & 3;
            float4 va = *(const float4*)(A  + (m0 + row) * K + k0 + c4 * 4);
            As[c4 * 4 + 0][row] = va.x; As[c4 * 4 + 1][row] = va.y;
            As[c4 * 4 + 2][row] = va.z; As[c4 * 4 + 3][row] = va.w;
            float4 vb = *(const float4*)(Bm + (size_t)(n0 + row) * K + k0 + c4 * 4);
            Bs[c4 * 4 + 0][row] = vb.x; Bs[c4 * 4 + 1][row] = vb.y;
            Bs[c4 * 4 + 2][row] = vb.z; Bs[c4 * 4 + 3][row] = vb.w;
        }
        __syncthreads();
#pragma unroll
        for (int kk = 0; kk < 16; kk++) {
            float a[8], b[8];
            *(float4*)(a)     = *(const float4*)&As[kk][ty * 8];
            *(float4*)(a + 4) = *(const float4*)&As[kk][ty * 8 + 4];
            *(float4*)(b)     = *(const float4*)&Bs[kk][tx * 8];
            *(float4*)(b + 4) = *(const float4*)&Bs[kk][tx * 8 + 4];
#pragma unroll
            for (int i = 0; i < 8; i++)
#pragma unroll
                for (int j = 0; j < 8; j++)
                    acc[i][j] = fmaf(a[i], b[j], acc[i][j]);
        }
        __syncthreads();
    }

    float bv[8];
#pragma unroll
    for (int j = 0; j < 8; j++) bv[j] = bias[n0 + tx * 8 + j];
#pragma unroll
    for (int i = 0; i < 8; i++) {
        size_t base = (m0 + ty * 8 + i) * N + n0 + tx * 8;
        float4 o0, o1;
        o0.x = acc[i][0] + bv[0]; o0.y = acc[i][1] + bv[1];
        o0.z = acc[i][2] + bv[2]; o0.w = acc[i][3] + bv[3];
        o1.x = acc[i][4] + bv[4]; o1.y = acc[i][5] + bv[5];
        o1.z = acc[i][6] + bv[6]; o1.w = acc[i][7] + bv[7];
        *(float4*)(C + base)     = o0;
        *(float4*)(C + base + 4) = o1;
    }
}

// ============================================================================
// Kernel 5: recurrence chunk [t0, t0+nsteps).
//
// ONE __syncthreads per step. Redundant consumer-owned finalize:
//   warp w (slice s=w&3) consumes only h[64s..64s+64). Both warps {s, s+4}
//   redundantly finalize that whole slice from the barrier-published partials
//   into a warp-PRIVATE hpriv[w][64] (lane l does rows 64s+l and 64s+32+l).
//   Intra-warp __syncwarp() replaces the old named barrier + shared-h
//   round-trip. hpriv needs no double buffer: reads (matvec) complete before
//   the barrier, writes (finalize) happen after it. part[] stays parity-
//   double-buffered. Only the rh==0 warp stores h to g_hall.
// Smem-W part packed as f32x2 (rows paired; Ws float4 == ulonglong2).
// R13 FIX: Ws column stride in ulonglong2 units is 256/4 = 64 (was 128 ->
// read past the smem allocation -> illegal memory access).
// ============================================================================
#define WS_FLOATS   (4 * 12 * 256)                 // 12288
#define PART_OFF    WS_FLOATS                      // part[2][4][256] = 2048
#define HPRIV_OFF   (PART_OFF + 2 * 4 * 256)       // hpriv[8][64]   = 512
#define RNN_SMEM_FLOATS (HPRIV_OFF + 8 * 64)       // 14848
#define RNN_SMEM_BYTES  (RNN_SMEM_FLOATS * 4)      // 59392

__global__ __launch_bounds__(256, 1) void rnn_chunk(int t0, int nsteps) {
    extern __shared__ float dsm[];
    float* Ws    = dsm;                 // [4][12][256]
    float* part  = dsm + PART_OFF;      // [pp][s][256]
    float* hpriv = dsm + HPRIV_OFF;     // [warp][64]

    int b = blockIdx.x;
    int tid = threadIdx.x;
    int w = tid >> 5, l = tid & 31;
    int s = w & 3, rh = w >> 2;
    int r0 = 128 * rh + 4 * l;          // matvec rows r0..r0+3
    int k0 = 64 * s;                    // k-slice base
    int fr0 = 64 * s + l;               // finalize rows (consumer-owned slice)
    int fr1 = fr0 + 32;

    // ---- W register slice: rows r0..r0+3, k in [k0, k0+52) ----
    unsigned long long w2[4][26];
#pragma unroll
    for (int j = 0; j < 4; j++) {
        const float4* wp = (const float4*)(g_W + (size_t)(r0 + j) * Hh + k0);
#pragma unroll
        for (int c = 0; c < 13; c++) {
            float4 v = wp[c];
            w2[j][2 * c]     = pack2(v.x, v.y);
            w2[j][2 * c + 1] = pack2(v.z, v.w);
        }
    }
    // ---- Ws[((ss*12)+mm)*256 + rr] = W[rr][64*ss + 52 + mm] ----
    for (int i = tid; i < WS_FLOATS; i += 256) {
        int grp = i / 256;              // 0..47 = ss*12 + mm
        int ss = grp / 12;
        int mm = grp % 12;
        int rr = i & 255;
        Ws[i] = g_W[(size_t)rr * Hh + 64 * ss + 52 + mm];
    }
    // ---- h state into private slice copy ----
    {
        float h0 = 0.f, h1 = 0.f;
        if (t0 > 0) {
            const float* hsrc = g_hall + (size_t)b * Tt * Hh + (size_t)(t0 - 1) * Hh;
            h0 = hsrc[fr0];
            h1 = hsrc[fr1];
        }
        hpriv[w * 64 + l]      = h0;
        hpriv[w * 64 + 32 + l] = h1;
    }
    __syncthreads();

    const float* xq0 = g_xproj + (size_t)b * Tt * Hh + fr0;
    const float* xq1 = g_xproj + (size_t)b * Tt * Hh + fr1;
    float*       hl0 = g_hall  + (size_t)b * Tt * Hh + fr0;
    float*       hl1 = g_hall  + (size_t)b * Tt * Hh + fr1;
    float xa0 = xq0[(size_t)t0 * Hh], xa1 = xq0[(size_t)(t0 + 1) * Hh];
    float xb0 = xq1[(size_t)t0 * Hh], xb1 = xq1[(size_t)(t0 + 1) * Hh];

    const float* hp = hpriv + w * 64;                 // own private h slice
    const ulonglong2* wsp = (const ulonglong2*)(Ws + (s * 12) * 256 + r0);

    int tend = t0 + nsteps;
    for (int t = t0; t < tend; t++) {
        int pp = t & 1;
        float xa2 = 0.f, xb2 = 0.f;
        if (t + 2 < tend) {
            xa2 = xq0[(size_t)(t + 2) * Hh];
            xb2 = xq1[(size_t)(t + 2) * Hh];
        }

        unsigned long long a0 = 0ull, a1 = 0ull, a2 = 0ull, a3 = 0ull;
        unsigned long long b01 = 0ull, b23 = 0ull;

        // h-hi quads for the smem part (uniform broadcasts)
        float4 hqA = *(const float4*)(hp + 52);
        float4 hqB = *(const float4*)(hp + 56);
        float4 hqC = *(const float4*)(hp + 60);

#pragma unroll
        for (int m = 0; m < 12; m++) {
            // reg-part chunk m: 8 fma2
            ulonglong2 hv = ((const ulonglong2*)hp)[m];
            fma2(a0, w2[0][2 * m], hv.x); fma2(a0, w2[0][2 * m + 1], hv.y);
            fma2(a1, w2[1][2 * m], hv.x); fma2(a1, w2[1][2 * m + 1], hv.y);
            fma2(a2, w2[2][2 * m], hv.x); fma2(a2, w2[2][2 * m + 1], hv.y);
            fma2(a3, w2[3][2 * m], hv.x); fma2(a3, w2[3][2 * m + 1], hv.y);

            // smem-part col m, rows packed: 2 fma2
            float hs = (m < 4) ? ((m & 3) == 0 ? hqA.x : (m & 3) == 1 ? hqA.y
                               : (m & 3) == 2 ? hqA.z : hqA.w)
                     : (m < 8) ? ((m & 3) == 0 ? hqB.x : (m & 3) == 1 ? hqB.y
                               : (m & 3) == 2 ? hqB.z : hqB.w)
                               : ((m & 3) == 0 ? hqC.x : (m & 3) == 1 ? hqC.y
                               : (m & 3) == 2 ? hqC.z : hqC.w);
            unsigned long long hs2 = pack2(hs, hs);
            ulonglong2 wsv = wsp[m * 64];             // col stride 256 floats = 64 ull2
            fma2(b01, wsv.x, hs2);
            fma2(b23, wsv.y, hs2);
        }
        // reg-part tail chunk c = 12 (k = 48..51)
        {
            ulonglong2 hv = ((const ulonglong2*)hp)[12];
            fma2(a0, w2[0][24], hv.x); fma2(a0, w2[0][25], hv.y);
            fma2(a1, w2[1][24], hv.x); fma2(a1, w2[1][25], hv.y);
            fma2(a2, w2[2][24], hv.x); fma2(a2, w2[2][25], hv.y);
            fma2(a3, w2[3][24], hv.x); fma2(a3, w2[3][25], hv.y);
        }

        float2 p0 = unpack2(a0), p1 = unpack2(a1);
        float2 p2 = unpack2(a2), p3 = unpack2(a3);
        float2 q01 = unpack2(b01), q23 = unpack2(b23);
        float4 o;
        o.x = p0.x + p0.y + q01.x;
        o.y = p1.x + p1.y + q01.y;
        o.z = p2.x + p2.y + q23.x;
        o.w = p3.x + p3.y + q23.y;
        *(float4*)(part + (pp * 4 + s) * 256 + r0) = o;
        __syncthreads();                              // partials visible (ONLY barrier)

        // redundant consumer-owned finalize: rows fr0, fr1 of own slice
        {
            const float* pb = part + pp * 1024;
            float sumA = ((pb[fr0] + pb[256 + fr0]) +
                          (pb[512 + fr0] + pb[768 + fr0])) + xa0;
            float sumB = ((pb[fr1] + pb[256 + fr1]) +
                          (pb[512 + fr1] + pb[768 + fr1])) + xb0;
            float vA, vB;
            asm("tanh.approx.f32 %0, %1;" : "=f"(vA) : "f"(sumA));
            asm("tanh.approx.f32 %0, %1;" : "=f"(vB) : "f"(sumB));
            hpriv[w * 64 + l]      = vA;              // own private copy
            hpriv[w * 64 + 32 + l] = vB;
            if (rh == 0) {                            // single writer to gmem
                hl0[(size_t)t * Hh] = vA;
                hl1[(size_t)t * Hh] = vB;
            }
            xa0 = xa1; xa1 = xa2;
            xb0 = xb1; xb1 = xb2;
        }
        __syncwarp();                                  // hpriv visible intra-warp
    }
}

// ============================================================================
// launch: fork-join two streams inside graph capture. Streams/events created
// once on the first call (before the harness's pre-capture baseline).
// ============================================================================
extern "C" void kernel_launch(void* const* d_in, const int* in_sizes, int n_in,
                              void* d_out, int out_size) {
    const float* x      = (const float*)d_in[0];
    const float* W_in   = (const float*)d_in[1];
    const float* b_in   = (const float*)d_in[2];
    const float* W_out  = (const float*)d_in[3];
    const float* b_out  = (const float*)d_in[4];
    const float* u_raw  = (const float*)d_in[5];
    const float* sigmas = (const float*)d_in[6];
    const float* v_raw  = (const float*)d_in[7];
    float* out = (float*)d_out;

    void* xp_v = nullptr;
    void* hall_v = nullptr;
    cudaGetSymbolAddress(&xp_v, g_xproj);
    cudaGetSymbolAddress(&hall_v, g_hall);
    float* xp = (float*)xp_v;
    float* hall = (float*)hall_v;

    // one-time setup (first call happens before the pre-capture baseline)
    static bool s_init = false;
    static cudaStream_t sA, sB;
    static cudaEvent_t ev0, evA, evB, evX[NCHUNK], evR[NCHUNK];
    if (!s_init) {
        cudaFuncSetAttribute(rnn_chunk,
                             cudaFuncAttributeMaxDynamicSharedMemorySize,
                             RNN_SMEM_BYTES);
        cudaStreamCreateWithFlags(&sA, cudaStreamNonBlocking);
        cudaStreamCreateWithFlags(&sB, cudaStreamNonBlocking);
        cudaEventCreateWithFlags(&ev0, cudaEventDisableTiming);
        cudaEventCreateWithFlags(&evA, cudaEventDisableTiming);
        cudaEventCreateWithFlags(&evB, cudaEventDisableTiming);
        for (int i = 0; i < NCHUNK; i++) {
            cudaEventCreateWithFlags(&evX[i], cudaEventDisableTiming);
            cudaEventCreateWithFlags(&evR[i], cudaEventDisableTiming);
        }
        s_init = true;
    }

    // fork from the harness's (captured) stream
    cudaEventRecord(ev0, 0);
    cudaStreamWaitEvent(sA, ev0, 0);
    cudaStreamWaitEvent(sB, ev0, 0);

    // Stream A: W preparation
    prep_kernel<<<512, 256, 0, sA>>>(u_raw, v_raw);
    chain_kernel<<<64, 256, 0, sA>>>();
    wgemm_kernel<<<256, 256, 0, sA>>>(sigmas);

    // Stream B: xproj chunks (independent of W chain)
    for (int i = 0; i < NCHUNK; i++) {
        sgemm_chunk<<<dim3(Hh / 128, Bb * TCDIV), 256, 0, sB>>>(
            x, W_in, b_in, xp, Hh, Ii, i * TCHUNK);
        cudaEventRecord(evX[i], sB);
    }

    // Stream A: recurrence chunks, each gated on its xproj chunk
    for (int i = 0; i < NCHUNK; i++) {
        cudaStreamWaitEvent(sA, evX[i], 0);
        rnn_chunk<<<Bb, 256, RNN_SMEM_BYTES, sA>>>(i * TCHUNK, TCHUNK);
        cudaEventRecord(evR[i], sA);
    }

    // Stream B: output-projection chunks, each gated on its rnn chunk
    for (int i = 0; i < NCHUNK; i++) {
        cudaStreamWaitEvent(sB, evR[i], 0);
        sgemm_chunk<<<dim3(Oo / 128, Bb * TCDIV), 256, 0, sB>>>(
            hall, W_out, b_out, out, Oo, Hh, i * TCHUNK);
    }

    // join both side streams back into the captured stream
    cudaEventRecord(evA, sA);
    cudaEventRecord(evB, sB);
    cudaStreamWaitEvent(0, evA, 0);
    cudaStreamWaitEvent(0, evB, 0);
}

// round 15
// speedup vs baseline: 1.5497x; 1.5497x over previous
#include <cuda_runtime.h>
#include <cstdint>
#include <cstddef>

// Problem constants
#define Bb 64
#define Tt 2048
#define Ii 128
#define Hh 256
#define Oo 128
#define Mm 256   // H - K1 + 1

#define NCHUNK 8
#define TCHUNK (Tt / NCHUNK)        // 256
#define TCDIV  (TCHUNK / 128)       // 2

// ---------------- scratch (device globals; no allocation allowed) ----------------
__device__ float g_uhats[Mm * Hh];
__device__ float g_vhats[Mm * Hh];
__device__ float g_bu[Mm];
__device__ float g_bv[Mm];
__device__ float g_U[Hh * Hh];
__device__ float g_V[Hh * Hh];
__device__ float g_W[Hh * Hh];
__device__ float g_xproj[(size_t)Bb * Tt * Hh];  // [B,T,H]
__device__ float g_hall [(size_t)Bb * Tt * Hh];  // [B,T,H]

// ---------------- packed f32x2 helpers ----------------
__device__ __forceinline__ unsigned long long pack2(float lo, float hi) {
    unsigned long long r;
    asm("mov.b64 %0, {%1, %2};" : "=l"(r) : "f"(lo), "f"(hi));
    return r;
}
__device__ __forceinline__ void fma2(unsigned long long& d,
                                     unsigned long long a,
                                     unsigned long long b) {
    asm("fma.rn.f32x2 %0, %1, %2, %0;" : "+l"(d) : "l"(a), "l"(b));
}
__device__ __forceinline__ float2 unpack2(unsigned long long v) {
    float lo, hi;
    asm("mov.b64 {%0, %1}, %2;" : "=f"(lo), "=f"(hi) : "l"(v));
    return make_float2(lo, hi);
}

// ============================================================================
// Kernel 1: build u_hats / v_hats (mask + flips) and betas = 2/<u,u>
// ============================================================================
__global__ __launch_bounds__(256) void prep_kernel(const float* __restrict__ u_raw,
                                                   const float* __restrict__ v_raw) {
    __shared__ float red[256];
    int i = blockIdx.x & 255;
    bool isv = blockIdx.x >= 256;
    int j = threadIdx.x;
    float val = 0.f;
    if (!isv) {
        if (j >= 255 - i) val = u_raw[i * Hh + (255 - j)];
        g_uhats[i * Hh + j] = val;
    } else {
        if (j >= i) val = v_raw[(255 - i) * Hh + (255 - j)];
        g_vhats[i * Hh + j] = val;
    }
    red[j] = val * val;
    __syncthreads();
    for (int s = 128; s > 0; s >>= 1) {
        if (j < s) red[j] += red[j + s];
        __syncthreads();
    }
    if (j == 0) {
        float beta = 2.f / red[0];
        if (isv) g_bv[i] = beta; else g_bu[i] = beta;
    }
}

// ============================================================================
// Kernel 2: Householder chains, one warp per column of U/V.
// ============================================================================
__global__ __launch_bounds__(256) void chain_kernel() {
    int warp = (blockIdx.x * blockDim.x + threadIdx.x) >> 5;
    int lane = threadIdx.x & 31;
    int col = warp & 255;
    bool isv = warp >= 256;
    const float* hats  = isv ? g_vhats : g_uhats;
    const float* betas = isv ? g_bv    : g_bu;
    float* out         = isv ? g_V     : g_U;

    float c[8];
#pragma unroll
    for (int q = 0; q < 8; q++) c[q] = ((lane + 32 * q) == col) ? 1.f : 0.f;

    for (int i = 0; i < Mm; i++) {
        float u[8];
#pragma unroll
        for (int q = 0; q < 8; q++) u[q] = hats[i * Hh + lane + 32 * q];
        float s = 0.f;
#pragma unroll
        for (int q = 0; q < 8; q++) s = fmaf(u[q], c[q], s);
#pragma unroll
        for (int off = 16; off > 0; off >>= 1)
            s += __shfl_xor_sync(0xffffffffu, s, off);
        float sc = betas[i] * s;
#pragma unroll
        for (int q = 0; q < 8; q++) c[q] = fmaf(-sc, u[q], c[q]);
    }
#pragma unroll
    for (int q = 0; q < 8; q++) out[(size_t)(lane + 32 * q) * Hh + col] = c[q];
}

// ============================================================================
// Kernel 3: W = (U * diag(sigmas)) @ V.
// ============================================================================
__global__ __launch_bounds__(256) void wgemm_kernel(const float* __restrict__ sig) {
    __shared__ float su[Hh];
    int r = blockIdx.x;
    int cidx = threadIdx.x;
    su[cidx] = g_U[r * Hh + cidx] * sig[cidx];
    __syncthreads();
    float acc = 0.f;
#pragma unroll 8
    for (int k = 0; k < Hh; k++) acc = fmaf(su[k], g_V[(size_t)k * Hh + cidx], acc);
    g_W[r * Hh + cidx] = acc;
}

// ============================================================================
// Kernel 4/6: chunked SGEMM.  C[m, n] = A[m, :K] . B[n, :K] + bias[n]
// ============================================================================
__global__ __launch_bounds__(256) void sgemm_chunk(const float* __restrict__ A,
                                                   const float* __restrict__ Bm,
                                                   const float* __restrict__ bias,
                                                   float* __restrict__ C,
                                                   int N, int K, int t0) {
    __shared__ float As[16][128];
    __shared__ float Bs[16][128];
    int tid = threadIdx.x;
    int bb = blockIdx.y / TCDIV;
    int tb = blockIdx.y % TCDIV;
    size_t m0 = (size_t)bb * Tt + t0 + tb * 128;
    int n0 = blockIdx.x * 128;
    int tx = tid & 15;
    int ty = tid >> 4;

    float acc[8][8];
#pragma unroll
    for (int i = 0; i < 8; i++)
#pragma unroll
        for (int j = 0; j < 8; j++) acc[i][j] = 0.f;

    for (int k0 = 0; k0 < K; k0 += 16) {
#pragma unroll
        for (int i = 0; i < 2; i++) {
            int fid = tid + i * 256;
            int row = fid >> 2;
            int c4  = fid & 3;
            float4 va = *(const float4*)(A  + (m0 + row) * K + k0 + c4 * 4);
            As[c4 * 4 + 0][row] = va.x; As[c4 * 4 + 1][row] = va.y;
            As[c4 * 4 + 2][row] = va.z; As[c4 * 4 + 3][row] = va.w;
            float4 vb = *(const float4*)(Bm + (size_t)(n0 + row) * K + k0 + c4 * 4);
            Bs[c4 * 4 + 0][row] = vb.x; Bs[c4 * 4 + 1][row] = vb.y;
            Bs[c4 * 4 + 2][row] = vb.z; Bs[c4 * 4 + 3][row] = vb.w;
        }
        __syncthreads();
#pragma unroll
        for (int kk = 0; kk < 16; kk++) {
            float a[8], b[8];
            *(float4*)(a)     = *(const float4*)&As[kk][ty * 8];
            *(float4*)(a + 4) = *(const float4*)&As[kk][ty * 8 + 4];
            *(float4*)(b)     = *(const float4*)&Bs[kk][tx * 8];
            *(float4*)(b + 4) = *(const float4*)&Bs[kk][tx * 8 + 4];
#pragma unroll
            for (int i = 0; i < 8; i++)
#pragma unroll
                for (int j = 0; j < 8; j++)
                    acc[i][j] = fmaf(a[i], b[j], acc[i][j]);
        }
        __syncthreads();
    }

    float bv[8];
#pragma unroll
    for (int j = 0; j < 8; j++) bv[j] = bias[n0 + tx * 8 + j];
#pragma unroll
    for (int i = 0; i < 8; i++) {
        size_t base = (m0 + ty * 8 + i) * N + n0 + tx * 8;
        float4 o0, o1;
        o0.x = acc[i][0] + bv[0]; o0.y = acc[i][1] + bv[1];
        o0.z = acc[i][2] + bv[2]; o0.w = acc[i][3] + bv[3];
        o1.x = acc[i][4] + bv[4]; o1.y = acc[i][5] + bv[5];
        o1.z = acc[i][6] + bv[6]; o1.w = acc[i][7] + bv[7];
        *(float4*)(C + base)     = o0;
        *(float4*)(C + base + 4) = o1;
    }
}

// ============================================================================
// Kernel 5: recurrence chunk [t0, t0+nsteps).  R11 protocol (known-good):
//   warp w: kslice s=w&3, rowhalf rh=w>>2; lane: rows r0..r0+3, 52 reg-cols
//   + 12 smem-W cols; partials -> __syncthreads -> per-pair finalize row fr
//   -> named bar.sync(1+s, 64). Shared hbuf double-buffered.
// R14 delta vs R11: smem-W part packed f32x2 (rows paired; correct ull2
// stride = 64 per column). No other body changes (R12/R13's extra live
// registers caused spills).
// ============================================================================
#define WS_FLOATS   (4 * 12 * 256)                 // 12288
#define PART_OFF    WS_FLOATS                      // part[2][4][256] = 2048
#define HBUF_OFF    (PART_OFF + 2 * 4 * 256)       // hbuf[2][256]   = 512
#define RNN_SMEM_FLOATS (HBUF_OFF + 2 * 256)       // 14848
#define RNN_SMEM_BYTES  (RNN_SMEM_FLOATS * 4)      // 59392

__global__ __launch_bounds__(256, 1) void rnn_chunk(int t0, int nsteps) {
    extern __shared__ float dsm[];
    float* Ws   = dsm;                 // [4][12][256]
    float* part = dsm + PART_OFF;      // [pp][s][256]
    float* hbuf = dsm + HBUF_OFF;      // [buf][256]

    int b = blockIdx.x;
    int tid = threadIdx.x;
    int w = tid >> 5, l = tid & 31;
    int s = w & 3, rh = w >> 2;
    int r0 = 128 * rh + 4 * l;         // matvec rows r0..r0+3
    int k0 = 64 * s;                   // k-slice base
    int fr = 64 * s + 32 * rh + l;     // finalize row (consumer-owned)

    // ---- W register slice: rows r0..r0+3, k in [k0, k0+52) ----
    unsigned long long w2[4][26];
#pragma unroll
    for (int j = 0; j < 4; j++) {
        const float4* wp = (const float4*)(g_W + (size_t)(r0 + j) * Hh + k0);
#pragma unroll
        for (int c = 0; c < 13; c++) {
            float4 v = wp[c];
            w2[j][2 * c]     = pack2(v.x, v.y);
            w2[j][2 * c + 1] = pack2(v.z, v.w);
        }
    }
    // ---- Ws[((ss*12)+mm)*256 + rr] = W[rr][64*ss + 52 + mm] ----
    for (int i = tid; i < WS_FLOATS; i += 256) {
        int grp = i / 256;             // 0..47 = ss*12 + mm
        int ss = grp / 12;
        int mm = grp % 12;
        int rr = i & 255;
        Ws[i] = g_W[(size_t)rr * Hh + 64 * ss + 52 + mm];
    }
    // ---- h state: zeros at t0==0, else h[t0-1] from g_hall ----
    if (t0 == 0) hbuf[tid] = 0.f;
    else         hbuf[tid] = g_hall[(size_t)b * Tt * Hh + (size_t)(t0 - 1) * Hh + tid];
    __syncthreads();

    // finalizer row = fr
    const float* xp_ptr   = g_xproj + (size_t)b * Tt * Hh + fr;
    float*       hall_ptr = g_hall  + (size_t)b * Tt * Hh + fr;
    float xp0 = xp_ptr[(size_t)t0 * Hh];
    float xp1 = xp_ptr[(size_t)(t0 + 1) * Hh];

    int cur = 0;
    int tend = t0 + nsteps;
    for (int t = t0; t < tend; t++) {
        int pp = t & 1;
        float xp2 = 0.f;
        if (t + 2 < tend) xp2 = xp_ptr[(size_t)(t + 2) * Hh];

        const float* h = hbuf + cur * 256 + k0;

        // register part: 26 packed fma2 per row
        unsigned long long a0 = 0ull, a1 = 0ull, a2 = 0ull, a3 = 0ull;
#pragma unroll
        for (int c = 0; c < 13; c++) {
            ulonglong2 hv = *(const ulonglong2*)(h + 4 * c);
            fma2(a0, w2[0][2 * c], hv.x); fma2(a0, w2[0][2 * c + 1], hv.y);
            fma2(a1, w2[1][2 * c], hv.x); fma2(a1, w2[1][2 * c + 1], hv.y);
            fma2(a2, w2[2][2 * c], hv.x); fma2(a2, w2[2][2 * c + 1], hv.y);
            fma2(a3, w2[3][2 * c], hv.x); fma2(a3, w2[3][2 * c + 1], hv.y);
        }

        // smem-W part: k = k0+52 .. k0+63, rows packed as f32x2
        unsigned long long b01 = 0ull, b23 = 0ull;
#pragma unroll
        for (int c = 0; c < 3; c++) {
            float4 hf = *(const float4*)(h + 52 + 4 * c);
            float hs[4] = {hf.x, hf.y, hf.z, hf.w};
#pragma unroll
            for (int m2 = 0; m2 < 4; m2++) {
                int m = 4 * c + m2;
                // (s*12+m)*256 + r0 floats; ull2 units: col stride 64
                ulonglong2 wsv = *(const ulonglong2*)(Ws + (s * 12 + m) * 256 + r0);
                unsigned long long hs2 = pack2(hs[m2], hs[m2]);
                fma2(b01, wsv.x, hs2);
                fma2(b23, wsv.y, hs2);
            }
        }

        float2 p0 = unpack2(a0), p1 = unpack2(a1);
        float2 p2 = unpack2(a2), p3 = unpack2(a3);
        float2 q01 = unpack2(b01), q23 = unpack2(b23);
        float4 o;
        o.x = p0.x + p0.y + q01.x;
        o.y = p1.x + p1.y + q01.y;
        o.z = p2.x + p2.y + q23.x;
        o.w = p3.x + p3.y + q23.y;
        *(float4*)(part + (pp * 4 + s) * 256 + r0) = o;
        __syncthreads();                           // all partials visible

        // finalize the rows THIS warp-pair will consume next step
        int nxt = cur ^ 1;
        {
            const float* pb = part + pp * 1024 + fr;
            float sum = ((pb[0] + pb[256]) + (pb[512] + pb[768])) + xp0;
            float v;
            asm("tanh.approx.f32 %0, %1;" : "=f"(v) : "f"(sum));
            hbuf[nxt * 256 + fr] = v;
            hall_ptr[(size_t)t * Hh] = v;          // deferred output projection
            xp0 = xp1; xp1 = xp2;
        }
        // sync only the 2 warps sharing k-slice s (ids 1..4, 64 threads)
        asm volatile("bar.sync %0, %1;" :: "r"(1 + s), "r"(64) : "memory");
        cur = nxt;
    }
}

// ============================================================================
// launch: fork-join two streams inside graph capture. Streams/events created
// once on the first call (before the harness's pre-capture baseline).
// Enqueue order puts rnn_chunk as the 6th kernel so ncu (-s 5 -c 1) finally
// profiles the RNN; events keep cross-stream semantics identical.
// ============================================================================
extern "C" void kernel_launch(void* const* d_in, const int* in_sizes, int n_in,
                              void* d_out, int out_size) {
    const float* x      = (const float*)d_in[0];
    const float* W_in   = (const float*)d_in[1];
    const float* b_in   = (const float*)d_in[2];
    const float* W_out  = (const float*)d_in[3];
    const float* b_out  = (const float*)d_in[4];
    const float* u_raw  = (const float*)d_in[5];
    const float* sigmas = (const float*)d_in[6];
    const float* v_raw  = (const float*)d_in[7];
    float* out = (float*)d_out;

    void* xp_v = nullptr;
    void* hall_v = nullptr;
    cudaGetSymbolAddress(&xp_v, g_xproj);
    cudaGetSymbolAddress(&hall_v, g_hall);
    float* xp = (float*)xp_v;
    float* hall = (float*)hall_v;

    // one-time setup (first call happens before the pre-capture baseline)
    static bool s_init = false;
    static cudaStream_t sA, sB;
    static cudaEvent_t ev0, evA, evB, evX[NCHUNK], evR[NCHUNK];
    if (!s_init) {
        cudaFuncSetAttribute(rnn_chunk,
                             cudaFuncAttributeMaxDynamicSharedMemorySize,
                             RNN_SMEM_BYTES);
        cudaStreamCreateWithFlags(&sA, cudaStreamNonBlocking);
        cudaStreamCreateWithFlags(&sB, cudaStreamNonBlocking);
        cudaEventCreateWithFlags(&ev0, cudaEventDisableTiming);
        cudaEventCreateWithFlags(&evA, cudaEventDisableTiming);
        cudaEventCreateWithFlags(&evB, cudaEventDisableTiming);
        for (int i = 0; i < NCHUNK; i++) {
            cudaEventCreateWithFlags(&evX[i], cudaEventDisableTiming);
            cudaEventCreateWithFlags(&evR[i], cudaEventDisableTiming);
        }
        s_init = true;
    }

    // fork from the harness's (captured) stream
    cudaEventRecord(ev0, 0);
    cudaStreamWaitEvent(sA, ev0, 0);
    cudaStreamWaitEvent(sB, ev0, 0);

    // Stream A: W preparation  (kernels #1..#3)
    prep_kernel<<<512, 256, 0, sA>>>(u_raw, v_raw);
    chain_kernel<<<64, 256, 0, sA>>>();
    wgemm_kernel<<<256, 256, 0, sA>>>(sigmas);

    // Stream B: first two xproj chunks (kernels #4, #5)
    for (int i = 0; i < 2; i++) {
        sgemm_chunk<<<dim3(Hh / 128, Bb * TCDIV), 256, 0, sB>>>(
            x, W_in, b_in, xp, Hh, Ii, i * TCHUNK);
        cudaEventRecord(evX[i], sB);
    }

    // Stream A: first rnn chunk (kernel #6 -> ncu -s 5 -c 1 captures THIS)
    cudaStreamWaitEvent(sA, evX[0], 0);
    rnn_chunk<<<Bb, 256, RNN_SMEM_BYTES, sA>>>(0, TCHUNK);
    cudaEventRecord(evR[0], sA);

    // Stream B: remaining xproj chunks
    for (int i = 2; i < NCHUNK; i++) {
        sgemm_chunk<<<dim3(Hh / 128, Bb * TCDIV), 256, 0, sB>>>(
            x, W_in, b_in, xp, Hh, Ii, i * TCHUNK);
        cudaEventRecord(evX[i], sB);
    }

    // Stream A: remaining rnn chunks
    for (int i = 1; i < NCHUNK; i++) {
        cudaStreamWaitEvent(sA, evX[i], 0);
        rnn_chunk<<<Bb, 256, RNN_SMEM_BYTES, sA>>>(i * TCHUNK, TCHUNK);
        cudaEventRecord(evR[i], sA);
    }

    // Stream B: output-projection chunks, each gated on its rnn chunk
    for (int i = 0; i < NCHUNK; i++) {
        cudaStreamWaitEvent(sB, evR[i], 0);
        sgemm_chunk<<<dim3(Oo / 128, Bb * TCDIV), 256, 0, sB>>>(
            hall, W_out, b_out, out, Oo, Hh, i * TCHUNK);
    }

    // join both side streams back into the captured stream
    cudaEventRecord(evA, sA);
    cudaEventRecord(evB, sB);
    cudaStreamWaitEvent(0, evA, 0);
    cudaStreamWaitEvent(0, evB, 0);
}

// round 16
// speedup vs baseline: 1.5931x; 1.0280x over previous
#include <cuda_runtime.h>
#include <cstdint>
#include <cstddef>

// Problem constants
#define Bb 64
#define Tt 2048
#define Ii 128
#define Hh 256
#define Oo 128
#define Mm 256   // H - K1 + 1

#define NCHUNK 8
#define TCHUNK (Tt / NCHUNK)        // 256
#define TCDIV  (TCHUNK / 128)       // 2

// ---------------- scratch (device globals; no allocation allowed) ----------------
__device__ float g_uhats[Mm * Hh];
__device__ float g_vhats[Mm * Hh];
__device__ float g_bu[Mm];
__device__ float g_bv[Mm];
__device__ float g_U[Hh * Hh];
__device__ float g_V[Hh * Hh];
__device__ float g_W[Hh * Hh];
__device__ float g_xproj[(size_t)Bb * Tt * Hh];  // [B,T,H]
__device__ float g_hall [(size_t)Bb * Tt * Hh];  // [B,T,H]

// ---------------- packed f32x2 helpers ----------------
__device__ __forceinline__ unsigned long long pack2(float lo, float hi) {
    unsigned long long r;
    asm("mov.b64 %0, {%1, %2};" : "=l"(r) : "f"(lo), "f"(hi));
    return r;
}
__device__ __forceinline__ void fma2(unsigned long long& d,
                                     unsigned long long a,
                                     unsigned long long b) {
    asm("fma.rn.f32x2 %0, %1, %2, %0;" : "+l"(d) : "l"(a), "l"(b));
}
__device__ __forceinline__ float2 unpack2(unsigned long long v) {
    float lo, hi;
    asm("mov.b64 {%0, %1}, %2;" : "=f"(lo), "=f"(hi) : "l"(v));
    return make_float2(lo, hi);
}

// ============================================================================
// Kernel 1: build u_hats / v_hats (mask + flips) and betas = 2/<u,u>
// ============================================================================
__global__ __launch_bounds__(256) void prep_kernel(const float* __restrict__ u_raw,
                                                   const float* __restrict__ v_raw) {
    __shared__ float red[256];
    int i = blockIdx.x & 255;
    bool isv = blockIdx.x >= 256;
    int j = threadIdx.x;
    float val = 0.f;
    if (!isv) {
        if (j >= 255 - i) val = u_raw[i * Hh + (255 - j)];
        g_uhats[i * Hh + j] = val;
    } else {
        if (j >= i) val = v_raw[(255 - i) * Hh + (255 - j)];
        g_vhats[i * Hh + j] = val;
    }
    red[j] = val * val;
    __syncthreads();
    for (int s = 128; s > 0; s >>= 1) {
        if (j < s) red[j] += red[j + s];
        __syncthreads();
    }
    if (j == 0) {
        float beta = 2.f / red[0];
        if (isv) g_bv[i] = beta; else g_bu[i] = beta;
    }
}

// ============================================================================
// Kernel 2: Householder chains, one warp per column of U/V.
// ============================================================================
__global__ __launch_bounds__(256) void chain_kernel() {
    int warp = (blockIdx.x * blockDim.x + threadIdx.x) >> 5;
    int lane = threadIdx.x & 31;
    int col = warp & 255;
    bool isv = warp >= 256;
    const float* hats  = isv ? g_vhats : g_uhats;
    const float* betas = isv ? g_bv    : g_bu;
    float* out         = isv ? g_V     : g_U;

    float c[8];
#pragma unroll
    for (int q = 0; q < 8; q++) c[q] = ((lane + 32 * q) == col) ? 1.f : 0.f;

    for (int i = 0; i < Mm; i++) {
        float u[8];
#pragma unroll
        for (int q = 0; q < 8; q++) u[q] = hats[i * Hh + lane + 32 * q];
        float s = 0.f;
#pragma unroll
        for (int q = 0; q < 8; q++) s = fmaf(u[q], c[q], s);
#pragma unroll
        for (int off = 16; off > 0; off >>= 1)
            s += __shfl_xor_sync(0xffffffffu, s, off);
        float sc = betas[i] * s;
#pragma unroll
        for (int q = 0; q < 8; q++) c[q] = fmaf(-sc, u[q], c[q]);
    }
#pragma unroll
    for (int q = 0; q < 8; q++) out[(size_t)(lane + 32 * q) * Hh + col] = c[q];
}

// ============================================================================
// Kernel 3: W = (U * diag(sigmas)) @ V.
// ============================================================================
__global__ __launch_bounds__(256) void wgemm_kernel(const float* __restrict__ sig) {
    __shared__ float su[Hh];
    int r = blockIdx.x;
    int cidx = threadIdx.x;
    su[cidx] = g_U[r * Hh + cidx] * sig[cidx];
    __syncthreads();
    float acc = 0.f;
#pragma unroll 8
    for (int k = 0; k < Hh; k++) acc = fmaf(su[k], g_V[(size_t)k * Hh + cidx], acc);
    g_W[r * Hh + cidx] = acc;
}

// ============================================================================
// Kernel 4/6: chunked SGEMM.  C[m, n] = A[m, :K] . B[n, :K] + bias[n]
// ============================================================================
__global__ __launch_bounds__(256) void sgemm_chunk(const float* __restrict__ A,
                                                   const float* __restrict__ Bm,
                                                   const float* __restrict__ bias,
                                                   float* __restrict__ C,
                                                   int N, int K, int t0) {
    __shared__ float As[16][128];
    __shared__ float Bs[16][128];
    int tid = threadIdx.x;
    int bb = blockIdx.y / TCDIV;
    int tb = blockIdx.y % TCDIV;
    size_t m0 = (size_t)bb * Tt + t0 + tb * 128;
    int n0 = blockIdx.x * 128;
    int tx = tid & 15;
    int ty = tid >> 4;

    float acc[8][8];
#pragma unroll
    for (int i = 0; i < 8; i++)
#pragma unroll
        for (int j = 0; j < 8; j++) acc[i][j] = 0.f;

    for (int k0 = 0; k0 < K; k0 += 16) {
#pragma unroll
        for (int i = 0; i < 2; i++) {
            int fid = tid + i * 256;
            int row = fid >> 2;
            int c4  = fid & 3;
            float4 va = *(const float4*)(A  + (m0 + row) * K + k0 + c4 * 4);
            As[c4 * 4 + 0][row] = va.x; As[c4 * 4 + 1][row] = va.y;
            As[c4 * 4 + 2][row] = va.z; As[c4 * 4 + 3][row] = va.w;
            float4 vb = *(const float4*)(Bm + (size_t)(n0 + row) * K + k0 + c4 * 4);
            Bs[c4 * 4 + 0][row] = vb.x; Bs[c4 * 4 + 1][row] = vb.y;
            Bs[c4 * 4 + 2][row] = vb.z; Bs[c4 * 4 + 3][row] = vb.w;
        }
        __syncthreads();
#pragma unroll
        for (int kk = 0; kk < 16; kk++) {
            float a[8], b[8];
            *(float4*)(a)     = *(const float4*)&As[kk][ty * 8];
            *(float4*)(a + 4) = *(const float4*)&As[kk][ty * 8 + 4];
            *(float4*)(b)     = *(const float4*)&Bs[kk][tx * 8];
            *(float4*)(b + 4) = *(const float4*)&Bs[kk][tx * 8 + 4];
#pragma unroll
            for (int i = 0; i < 8; i++)
#pragma unroll
                for (int j = 0; j < 8; j++)
                    acc[i][j] = fmaf(a[i], b[j], acc[i][j]);
        }
        __syncthreads();
    }

    float bv[8];
#pragma unroll
    for (int j = 0; j < 8; j++) bv[j] = bias[n0 + tx * 8 + j];
#pragma unroll
    for (int i = 0; i < 8; i++) {
        size_t base = (m0 + ty * 8 + i) * N + n0 + tx * 8;
        float4 o0, o1;
        o0.x = acc[i][0] + bv[0]; o0.y = acc[i][1] + bv[1];
        o0.z = acc[i][2] + bv[2]; o0.w = acc[i][3] + bv[3];
        o1.x = acc[i][4] + bv[4]; o1.y = acc[i][5] + bv[5];
        o1.z = acc[i][6] + bv[6]; o1.w = acc[i][7] + bv[7];
        *(float4*)(C + base)     = o0;
        *(float4*)(C + base + 4) = o1;
    }
}

// ============================================================================
// Kernel 5: recurrence chunk [t0, t0+nsteps).  R11-EXACT body (best measured):
// pipelined Ws double-buffer interleaved into reg-part fma2 stream; plain
// fmaf smem-W part; finalize-by-consumer + named bar.sync(1+s, 64).
// ============================================================================
#define WS_FLOATS   (4 * 12 * 256)                 // 12288
#define PART_OFF    WS_FLOATS                      // part[2][4][256] = 2048
#define HBUF_OFF    (PART_OFF + 2 * 4 * 256)       // hbuf[2][256]   = 512
#define RNN_SMEM_FLOATS (HBUF_OFF + 2 * 256)       // 14848
#define RNN_SMEM_BYTES  (RNN_SMEM_FLOATS * 4)      // 59392

__global__ __launch_bounds__(256, 1) void rnn_chunk(int t0, int nsteps) {
    extern __shared__ float dsm[];
    float* Ws   = dsm;                 // [4][12][256]
    float* part = dsm + PART_OFF;      // [pp][s][256]
    float* hbuf = dsm + HBUF_OFF;      // [buf][256]

    int b = blockIdx.x;
    int tid = threadIdx.x;
    int w = tid >> 5, l = tid & 31;
    int s = w & 3, rh = w >> 2;
    int r0 = 128 * rh + 4 * l;         // matvec rows r0..r0+3
    int k0 = 64 * s;                   // k-slice base
    int fr = 64 * s + 32 * rh + l;     // finalize row (consumer-owned)

    // ---- W register slice: rows r0..r0+3, k in [k0, k0+52) ----
    unsigned long long w2[4][26];
#pragma unroll
    for (int j = 0; j < 4; j++) {
        const float4* wp = (const float4*)(g_W + (size_t)(r0 + j) * Hh + k0);
#pragma unroll
        for (int c = 0; c < 13; c++) {
            float4 v = wp[c];
            w2[j][2 * c]     = pack2(v.x, v.y);
            w2[j][2 * c + 1] = pack2(v.z, v.w);
        }
    }
    // ---- Ws[((ss*12)+mm)*256 + rr] = W[rr][64*ss + 52 + mm] ----
    for (int i = tid; i < WS_FLOATS; i += 256) {
        int grp = i / 256;             // 0..47 = ss*12 + mm
        int ss = grp / 12;
        int mm = grp % 12;
        int rr = i & 255;
        Ws[i] = g_W[(size_t)rr * Hh + 64 * ss + 52 + mm];
    }
    // ---- h state: zeros at t0==0, else h[t0-1] from g_hall ----
    if (t0 == 0) hbuf[tid] = 0.f;
    else         hbuf[tid] = g_hall[(size_t)b * Tt * Hh + (size_t)(t0 - 1) * Hh + tid];
    __syncthreads();

    // finalizer row = fr
    const float* xp_ptr   = g_xproj + (size_t)b * Tt * Hh + fr;
    float*       hall_ptr = g_hall  + (size_t)b * Tt * Hh + fr;
    float xp0 = xp_ptr[(size_t)t0 * Hh];
    float xp1 = xp_ptr[(size_t)(t0 + 1) * Hh];

    const float* wsp = Ws + (s * 12) * 256 + r0;   // this thread's Ws column base

    int cur = 0;
    int tend = t0 + nsteps;
    for (int t = t0; t < tend; t++) {
        int pp = t & 1;
        float xp2 = 0.f;
        if (t + 2 < tend) xp2 = xp_ptr[(size_t)(t + 2) * Hh];

        const float* h = hbuf + cur * 256 + k0;

        unsigned long long a0 = 0ull, a1 = 0ull, a2 = 0ull, a3 = 0ull;
        float b0 = 0.f, b1 = 0.f, b2 = 0.f, b3 = 0.f;

        // pipelined step body: Ws loads interleave with reg-part fma2
        float4 wsA = *(const float4*)(wsp);          // m=0
        float4 wsB;
        float4 hq = *(const float4*)(h + 52);        // h[52..55]
#pragma unroll
        for (int m = 0; m < 12; m++) {
            // prefetch next Ws column (double buffer)
            if (m + 1 < 12) {
                if ((m & 1) == 0) wsB = *(const float4*)(wsp + (m + 1) * 256);
                else              wsA = *(const float4*)(wsp + (m + 1) * 256);
            }
            // reload h-hi quad when crossing a float4 boundary
            if (m == 4) hq = *(const float4*)(h + 56);
            if (m == 8) hq = *(const float4*)(h + 60);

            // reg-part chunk c = m: 8 fma2
            ulonglong2 hv = *(const ulonglong2*)(h + 4 * m);
            fma2(a0, w2[0][2 * m], hv.x); fma2(a0, w2[0][2 * m + 1], hv.y);
            fma2(a1, w2[1][2 * m], hv.x); fma2(a1, w2[1][2 * m + 1], hv.y);
            fma2(a2, w2[2][2 * m], hv.x); fma2(a2, w2[2][2 * m + 1], hv.y);
            fma2(a3, w2[3][2 * m], hv.x); fma2(a3, w2[3][2 * m + 1], hv.y);

            // smem-part col m (uses the Ws quad loaded last iteration)
            float hs = (m & 3) == 0 ? hq.x : (m & 3) == 1 ? hq.y
                     : (m & 3) == 2 ? hq.z : hq.w;
            float4 ws = ((m & 1) == 0) ? wsA : wsB;
            b0 = fmaf(ws.x, hs, b0);
            b1 = fmaf(ws.y, hs, b1);
            b2 = fmaf(ws.z, hs, b2);
            b3 = fmaf(ws.w, hs, b3);
        }
        // reg-part tail chunk c = 12
        {
            ulonglong2 hv = *(const ulonglong2*)(h + 48);
            fma2(a0, w2[0][24], hv.x); fma2(a0, w2[0][25], hv.y);
            fma2(a1, w2[1][24], hv.x); fma2(a1, w2[1][25], hv.y);
            fma2(a2, w2[2][24], hv.x); fma2(a2, w2[2][25], hv.y);
            fma2(a3, w2[3][24], hv.x); fma2(a3, w2[3][25], hv.y);
        }

        float2 p0 = unpack2(a0), p1 = unpack2(a1);
        float2 p2 = unpack2(a2), p3 = unpack2(a3);
        float4 o;
        o.x = p0.x + p0.y + b0;
        o.y = p1.x + p1.y + b1;
        o.z = p2.x + p2.y + b2;
        o.w = p3.x + p3.y + b3;
        *(float4*)(part + (pp * 4 + s) * 256 + r0) = o;
        __syncthreads();                           // all partials visible

        // finalize the rows THIS warp-pair will consume next step
        int nxt = cur ^ 1;
        {
            const float* pb = part + pp * 1024 + fr;
            float sum = ((pb[0] + pb[256]) + (pb[512] + pb[768])) + xp0;
            float v;
            asm("tanh.approx.f32 %0, %1;" : "=f"(v) : "f"(sum));
            hbuf[nxt * 256 + fr] = v;
            hall_ptr[(size_t)t * Hh] = v;          // deferred output projection
            xp0 = xp1; xp1 = xp2;
        }
        // sync only the 2 warps sharing k-slice s (ids 1..4, 64 threads)
        asm volatile("bar.sync %0, %1;" :: "r"(1 + s), "r"(64) : "memory");
        cur = nxt;
    }
}

// ============================================================================
// launch: fork-join two streams inside graph capture. Streams/events created
// once on the first call (before the harness's pre-capture baseline).
//
// NCU pinning: sgemm4_2 waits on evR[0] (rnn0 completion). Exactly five
// kernels (prep, chain, wgemm, sg4_0, sg4_1) can precede rnn0 in ANY
// topological order, so the 6th executed kernel -- the one ncu -s 5 -c 1
// captures -- is guaranteed to be rnn_chunk. Timing cost ~0: sg4_2..7 shift
// to after rnn0 (~258us) but complete (~475us) long before their consumers
// rnn_2..7 (>=441us).
// ============================================================================
extern "C" void kernel_launch(void* const* d_in, const int* in_sizes, int n_in,
                              void* d_out, int out_size) {
    const float* x      = (const float*)d_in[0];
    const float* W_in   = (const float*)d_in[1];
    const float* b_in   = (const float*)d_in[2];
    const float* W_out  = (const float*)d_in[3];
    const float* b_out  = (const float*)d_in[4];
    const float* u_raw  = (const float*)d_in[5];
    const float* sigmas = (const float*)d_in[6];
    const float* v_raw  = (const float*)d_in[7];
    float* out = (float*)d_out;

    void* xp_v = nullptr;
    void* hall_v = nullptr;
    cudaGetSymbolAddress(&xp_v, g_xproj);
    cudaGetSymbolAddress(&hall_v, g_hall);
    float* xp = (float*)xp_v;
    float* hall = (float*)hall_v;

    // one-time setup (first call happens before the pre-capture baseline)
    static bool s_init = false;
    static cudaStream_t sA, sB;
    static cudaEvent_t ev0, evA, evB, evX[NCHUNK], evR[NCHUNK];
    if (!s_init) {
        cudaFuncSetAttribute(rnn_chunk,
                             cudaFuncAttributeMaxDynamicSharedMemorySize,
                             RNN_SMEM_BYTES);
        cudaStreamCreateWithFlags(&sA, cudaStreamNonBlocking);
        cudaStreamCreateWithFlags(&sB, cudaStreamNonBlocking);
        cudaEventCreateWithFlags(&ev0, cudaEventDisableTiming);
        cudaEventCreateWithFlags(&evA, cudaEventDisableTiming);
        cudaEventCreateWithFlags(&evB, cudaEventDisableTiming);
        for (int i = 0; i < NCHUNK; i++) {
            cudaEventCreateWithFlags(&evX[i], cudaEventDisableTiming);
            cudaEventCreateWithFlags(&evR[i], cudaEventDisableTiming);
        }
        s_init = true;
    }

    // fork from the harness's (captured) stream
    cudaEventRecord(ev0, 0);
    cudaStreamWaitEvent(sA, ev0, 0);
    cudaStreamWaitEvent(sB, ev0, 0);

    // Stream A: W preparation  (kernels #1..#3)
    prep_kernel<<<512, 256, 0, sA>>>(u_raw, v_raw);
    chain_kernel<<<64, 256, 0, sA>>>();
    wgemm_kernel<<<256, 256, 0, sA>>>(sigmas);

    // Stream B: first two xproj chunks (kernels #4, #5)
    for (int i = 0; i < 2; i++) {
        sgemm_chunk<<<dim3(Hh / 128, Bb * TCDIV), 256, 0, sB>>>(
            x, W_in, b_in, xp, Hh, Ii, i * TCHUNK);
        cudaEventRecord(evX[i], sB);
    }

    // Stream A: first rnn chunk (#6 in every topological order)
    cudaStreamWaitEvent(sA, evX[0], 0);
    rnn_chunk<<<Bb, 256, RNN_SMEM_BYTES, sA>>>(0, TCHUNK);
    cudaEventRecord(evR[0], sA);

    // Stream B: remaining xproj chunks, gated behind rnn0 (ncu pinning edge)
    cudaStreamWaitEvent(sB, evR[0], 0);
    for (int i = 2; i < NCHUNK; i++) {
        sgemm_chunk<<<dim3(Hh / 128, Bb * TCDIV), 256, 0, sB>>>(
            x, W_in, b_in, xp, Hh, Ii, i * TCHUNK);
        cudaEventRecord(evX[i], sB);
    }

    // Stream A: remaining rnn chunks
    for (int i = 1; i < NCHUNK; i++) {
        cudaStreamWaitEvent(sA, evX[i], 0);
        rnn_chunk<<<Bb, 256, RNN_SMEM_BYTES, sA>>>(i * TCHUNK, TCHUNK);
        cudaEventRecord(evR[i], sA);
    }

    // Stream B: output-projection chunks, each gated on its rnn chunk
    for (int i = 0; i < NCHUNK; i++) {
        cudaStreamWaitEvent(sB, evR[i], 0);
        sgemm_chunk<<<dim3(Oo / 128, Bb * TCDIV), 256, 0, sB>>>(
            hall, W_out, b_out, out, Oo, Hh, i * TCHUNK);
    }

    // join both side streams back into the captured stream
    cudaEventRecord(evA, sA);
    cudaEventRecord(evB, sB);
    cudaStreamWaitEvent(0, evA, 0);
    cudaStreamWaitEvent(0, evB, 0);
}